// round 1
// baseline (speedup 1.0000x reference)
#include <cuda_runtime.h>
#include <cstdint>
#include <cstddef>

#define N_ATOMS 10000
#define N_PAIRS 250000
#define NP 128
#define NO 128

// Output layout in d_out (floats):
//   [0, 3.84M)                px_new  [N_ATOMS,3,NP]
//   [3.84M, 99.84M)           ix      [N_PAIRS,3,NP]
//   [99.84M, 101.12M)         dotted  [N_ATOMS,NO]
#define PXNEW_OFF ((size_t)0)
#define IX_OFF    ((size_t)N_ATOMS * 3 * NP)
#define DOT_OFF   (IX_OFF + (size_t)N_PAIRS * 3 * NP)

// ---- device scratch (allocation-free) ----
__device__ int g_count[N_ATOMS];
__device__ int g_offset[N_ATOMS + 1];
__device__ int g_cursor[N_ATOMS];
__device__ int g_pairs[N_PAIRS];

// ---------------------------------------------------------------------------
// K0: zero histogram
__global__ void k_zero() {
    int i = blockIdx.x * blockDim.x + threadIdx.x;
    if (i < N_ATOMS) g_count[i] = 0;
}

// K1: histogram of ind_i
__global__ void k_hist(const int* __restrict__ ind2) {
    int p = blockIdx.x * blockDim.x + threadIdx.x;
    if (p < N_PAIRS) atomicAdd(&g_count[ind2[2 * p]], 1);
}

// K2: exclusive prefix sum over 10000 counts (single block, 1024 threads)
__global__ void k_scan() {
    __shared__ int sb[1024];
    const int CH = 10;                       // 1024*10 >= 10000
    int t = threadIdx.x;
    int base = t * CH;
    int c[CH];
    int local = 0;
#pragma unroll
    for (int i = 0; i < CH; i++) {
        int idx = base + i;
        c[i] = (idx < N_ATOMS) ? g_count[idx] : 0;
        local += c[i];
    }
    sb[t] = local;
    __syncthreads();
    // Hillis-Steele inclusive scan
    for (int o = 1; o < 1024; o <<= 1) {
        int v = (t >= o) ? sb[t - o] : 0;
        __syncthreads();
        sb[t] += v;
        __syncthreads();
    }
    int run = sb[t] - local;                 // exclusive base
#pragma unroll
    for (int i = 0; i < CH; i++) {
        int idx = base + i;
        if (idx < N_ATOMS) {
            g_offset[idx] = run;
            g_cursor[idx] = run;
            run += c[i];
        }
    }
    if (t == 1023) g_offset[N_ATOMS] = sb[1023];
}

// K3: scatter pair ids into CSR buckets
__global__ void k_scatter(const int* __restrict__ ind2) {
    int p = blockIdx.x * blockDim.x + threadIdx.x;
    if (p < N_PAIRS) {
        int pos = atomicAdd(&g_cursor[ind2[2 * p]], 1);
        g_pairs[pos] = p;
    }
}

// ---------------------------------------------------------------------------
// K4: fused per-atom kernel.
//   block = one atom segment. 128 threads = 4 pair-groups (y) x 32 lanes (l).
//   Lane l owns channels [4l, 4l+4) (float4).
//   Phase 1: loop pairs (strided by y): compute ix, store it, accumulate.
//   Phase 2: reduce partials, GEMM with w_pp, self-dot, store px_new/dotted.
#define MAX_SEG 512

__global__ void __launch_bounds__(128, 8)
k_main(const int* __restrict__ ind2,
       const float* __restrict__ px,
       const float* __restrict__ i1,
       const float* __restrict__ diff,
       const float* __restrict__ wpp,
       float* __restrict__ out) {
    __shared__ int s_pairs[MAX_SEG];
    __shared__ __align__(16) float s_part[4][3][NP];   // per-y partials (reused in GEMM)
    __shared__ __align__(16) float s_fin[3][NP];       // reduced segment sum

    const int a = blockIdx.x;
    const int t = threadIdx.x;
    const int l = t & 31;        // lane -> channel group
    const int y = t >> 5;        // pair-parallel group
    const int q0 = 4 * l;

    const int beg = g_offset[a];
    const int cnt = g_offset[a + 1] - beg;

    // stage pair list into smem
    for (int k = t; k < cnt && k < MAX_SEG; k += 128) s_pairs[k] = g_pairs[beg + k];
    __syncthreads();

    // deterministic order: odd-even transposition sort by warp 0
    if (t < 32 && cnt > 1 && cnt <= MAX_SEG) {
        for (int r = 0; r < cnt; r++) {
            int start = r & 1;
            for (int idx = l; 2 * idx + 1 + start < cnt; idx += 32) {
                int ia = 2 * idx + start, ib = ia + 1;
                int va = s_pairs[ia], vb = s_pairs[ib];
                if (va > vb) { s_pairs[ia] = vb; s_pairs[ib] = va; }
            }
            __syncwarp();
        }
    }
    __syncthreads();

    float* out_ix = out + IX_OFF;

    float4 acc0 = make_float4(0.f, 0.f, 0.f, 0.f);
    float4 acc1 = acc0, acc2 = acc0;

    for (int k = y; k < cnt; k += 4) {
        int pr = (k < MAX_SEG) ? s_pairs[k] : g_pairs[beg + k];
        int j  = ind2[2 * pr + 1];
        const float* i1p = i1 + (size_t)pr * NP + q0;
        float4 s = *(const float4*)i1p;
        float d0 = diff[3 * pr + 0];
        float d1 = diff[3 * pr + 1];
        float d2 = diff[3 * pr + 2];
        const float* pj = px + (size_t)j * 3 * NP + q0;
        float4 p0 = *(const float4*)(pj);
        float4 p1 = *(const float4*)(pj + NP);
        float4 p2 = *(const float4*)(pj + 2 * NP);

        float4 v0, v1, v2;
        v0.x = (p0.x + d0) * s.x; v0.y = (p0.y + d0) * s.y;
        v0.z = (p0.z + d0) * s.z; v0.w = (p0.w + d0) * s.w;
        v1.x = (p1.x + d1) * s.x; v1.y = (p1.y + d1) * s.y;
        v1.z = (p1.z + d1) * s.z; v1.w = (p1.w + d1) * s.w;
        v2.x = (p2.x + d2) * s.x; v2.y = (p2.y + d2) * s.y;
        v2.z = (p2.z + d2) * s.z; v2.w = (p2.w + d2) * s.w;

        float* op = out_ix + (size_t)pr * 3 * NP + q0;
        *(float4*)(op)          = v0;
        *(float4*)(op + NP)     = v1;
        *(float4*)(op + 2 * NP) = v2;

        acc0.x += v0.x; acc0.y += v0.y; acc0.z += v0.z; acc0.w += v0.w;
        acc1.x += v1.x; acc1.y += v1.y; acc1.z += v1.z; acc1.w += v1.w;
        acc2.x += v2.x; acc2.y += v2.y; acc2.z += v2.z; acc2.w += v2.w;
    }

    *(float4*)&s_part[y][0][q0] = acc0;
    *(float4*)&s_part[y][1][q0] = acc1;
    *(float4*)&s_part[y][2][q0] = acc2;
    __syncthreads();

    // reduce 4 partials -> s_fin  (thread t owns channel t)
    {
        float f0 = s_part[0][0][t] + s_part[1][0][t] + s_part[2][0][t] + s_part[3][0][t];
        float f1 = s_part[0][1][t] + s_part[1][1][t] + s_part[2][1][t] + s_part[3][1][t];
        float f2 = s_part[0][2][t] + s_part[1][2][t] + s_part[2][2][t] + s_part[3][2][t];
        s_fin[0][t] = f0; s_fin[1][t] = f1; s_fin[2][t] = f2;
    }
    __syncthreads();

    // GEMM: px_new[a][x][q] = sum_p s_fin[x][p] * wpp[p][q]
    // thread (l,y): output channels q0..q0+3, p-range [32y, 32y+32)
    float4 o0 = make_float4(0.f, 0.f, 0.f, 0.f);
    float4 o1 = o0, o2 = o0;
#pragma unroll 8
    for (int pp = 0; pp < 32; pp++) {
        int p = (y << 5) + pp;
        float4 w = *(const float4*)&wpp[(size_t)p * NO + q0];
        float a0 = s_fin[0][p], a1 = s_fin[1][p], a2 = s_fin[2][p];
        o0.x += a0 * w.x; o0.y += a0 * w.y; o0.z += a0 * w.z; o0.w += a0 * w.w;
        o1.x += a1 * w.x; o1.y += a1 * w.y; o1.z += a1 * w.z; o1.w += a1 * w.w;
        o2.x += a2 * w.x; o2.y += a2 * w.y; o2.z += a2 * w.z; o2.w += a2 * w.w;
    }
    __syncthreads();   // s_part reuse
    *(float4*)&s_part[y][0][q0] = o0;
    *(float4*)&s_part[y][1][q0] = o1;
    *(float4*)&s_part[y][2][q0] = o2;
    __syncthreads();

    // reduce GEMM partials over y, write px_new and dotted
    {
        float r0 = s_part[0][0][t] + s_part[1][0][t] + s_part[2][0][t] + s_part[3][0][t];
        float r1 = s_part[0][1][t] + s_part[1][1][t] + s_part[2][1][t] + s_part[3][1][t];
        float r2 = s_part[0][2][t] + s_part[1][2][t] + s_part[2][2][t] + s_part[3][2][t];
        float* opx = out + PXNEW_OFF + (size_t)a * 3 * NP + t;
        opx[0]      = r0;
        opx[NP]     = r1;
        opx[2 * NP] = r2;
        out[DOT_OFF + (size_t)a * NO + t] = r0 * r0 + r1 * r1 + r2 * r2;
    }
}

// ---------------------------------------------------------------------------
extern "C" void kernel_launch(void* const* d_in, const int* in_sizes, int n_in,
                              void* d_out, int out_size) {
    const int*   ind2 = (const int*)d_in[0];
    const float* px   = (const float*)d_in[1];
    const float* i1   = (const float*)d_in[2];
    const float* diff = (const float*)d_in[3];
    const float* wpp  = (const float*)d_in[4];
    float* out = (float*)d_out;

    k_zero<<<(N_ATOMS + 255) / 256, 256>>>();
    k_hist<<<(N_PAIRS + 255) / 256, 256>>>(ind2);
    k_scan<<<1, 1024>>>();
    k_scatter<<<(N_PAIRS + 255) / 256, 256>>>(ind2);
    k_main<<<N_ATOMS, 128>>>(ind2, px, i1, diff, wpp, out);
}